// round 14
// baseline (speedup 1.0000x reference)
#include <cuda_runtime.h>
#include <math.h>

#define BB   8
#define CC   64
#define NPIX 4096   // 64*64

typedef unsigned long long u64;

// ---------------- scratch (static device globals; no allocation) ----------------
__device__ float g_mean[BB * CC];
__device__ float g_energy[BB * CC];
__device__ float g_scale[BB * CC];

__device__ __forceinline__ float sigm_(float v) { return __fdividef(1.f, 1.f + __expf(-v)); }
__device__ __forceinline__ float silu_(float v) { return v * __fdividef(1.f, 1.f + __expf(-v)); }

// ---------------- packed fp32x2 helpers (FFMA2 path, sm_100+) ----------------
__device__ __forceinline__ u64 pack2_(float lo, float hi) {
    u64 r; asm("mov.b64 %0, {%1, %2};" : "=l"(r) : "f"(lo), "f"(hi)); return r;
}
__device__ __forceinline__ u64 pack1_(float v) {
    u64 r; asm("mov.b64 %0, {%1, %1};" : "=l"(r) : "f"(v)); return r;
}
__device__ __forceinline__ void unpack2_(u64 p, float& lo, float& hi) {
    asm("mov.b64 {%0, %1}, %2;" : "=f"(lo), "=f"(hi) : "l"(p));
}
__device__ __forceinline__ u64 fma2_(u64 a, u64 b, u64 c) {
    u64 d; asm("fma.rn.f32x2 %0, %1, %2, %3;" : "=l"(d) : "l"(a), "l"(b), "l"(c)); return d;
}
__device__ __forceinline__ u64 add2_(u64 a, u64 b) {
    u64 d; asm("add.rn.f32x2 %0, %1, %2;" : "=l"(d) : "l"(a), "l"(b)); return d;
}

// ---------------- complex helpers (forward convention e^{-2pi i}) ----------------
__device__ __forceinline__ float2 cadd_(float2 a, float2 b) { return make_float2(a.x + b.x, a.y + b.y); }
__device__ __forceinline__ float2 csub_(float2 a, float2 b) { return make_float2(a.x - b.x, a.y - b.y); }
__device__ __forceinline__ float2 cmul_(float2 a, float2 b) {
    return make_float2(a.x * b.x - a.y * b.y, a.x * b.y + a.y * b.x);
}
__device__ __forceinline__ float2 cmni_(float2 a) { return make_float2(a.y, -a.x); }   // a * (-i)

// 8-point forward DFT, natural order in/out.
__device__ __forceinline__ void fft8_(const float2* z, float2* y)
{
    const float Cq = 0.70710678118654752f;
    float2 t0 = cadd_(z[0], z[4]), t1 = csub_(z[0], z[4]);
    float2 t2 = cadd_(z[2], z[6]), t3 = csub_(z[2], z[6]);
    float2 E0 = cadd_(t0, t2), E2 = csub_(t0, t2);
    float2 it3 = cmni_(t3);
    float2 E1 = cadd_(t1, it3), E3 = csub_(t1, it3);
    float2 u0 = cadd_(z[1], z[5]), u1 = csub_(z[1], z[5]);
    float2 u2 = cadd_(z[3], z[7]), u3 = csub_(z[3], z[7]);
    float2 O0 = cadd_(u0, u2), O2 = csub_(u0, u2);
    float2 iu3 = cmni_(u3);
    float2 O1 = cadd_(u1, iu3), O3 = csub_(u1, iu3);
    float2 W1O1 = make_float2(Cq * (O1.x + O1.y), Cq * (O1.y - O1.x));
    float2 W2O2 = cmni_(O2);
    float2 W3O3 = make_float2(Cq * (O3.y - O3.x), -Cq * (O3.x + O3.y));
    y[0] = cadd_(E0, O0);   y[4] = csub_(E0, O0);
    y[1] = cadd_(E1, W1O1); y[5] = csub_(E1, W1O1);
    y[2] = cadd_(E2, W2O2); y[6] = csub_(E2, W2O2);
    y[3] = cadd_(E3, W3O3); y[7] = csub_(E3, W3O3);
}

// ==================================================================================
// Kernel 1: per-(b,c) 64x64 FFT2 magnitude mean + spatial mean, radix-8 FFT.
// Reductions via warp shuffle (1 barrier each instead of 8).
// ==================================================================================
__global__ __launch_bounds__(256) void fft_energy_kernel(const float* __restrict__ x)
{
    __shared__ __align__(16) float sA[4352];   // xs -> Zs -> D
    __shared__ __align__(16) float sB[4352];   // C  -> As
    __shared__ float ct[64], st[64];
    __shared__ float red[8];

    const int tid = threadIdx.x;
    const int bc  = blockIdx.x;

    if (tid < 64) {
        float sv, cv;
        sincosf(0.09817477042468103f * (float)tid, &sv, &cv);   // 2*pi/64 * tid
        ct[tid] = cv;
        st[tid] = sv;
    }

    float* xs = sA;
    const float* xp = x + (size_t)bc * NPIX;
    float lsum = 0.f;
    for (int i = tid; i < 4096; i += 256) {
        float v = xp[i];
        xs[i] = v;
        lsum += v;
    }
#pragma unroll
    for (int o = 16; o; o >>= 1) lsum += __shfl_xor_sync(0xffffffffu, lsum, o);
    if ((tid & 31) == 0) red[tid >> 5] = lsum;
    __syncthreads();
    if (tid == 0) {
        float s = 0.f;
#pragma unroll
        for (int i = 0; i < 8; i++) s += red[i];
        g_mean[bc] = s * (1.f / 4096.f);
    }

    // ---- P1A: 256 tasks = (pair p, n0). z[n1] = row2p + i*row2p+1 at n0+8n1.
    {
        const int p  = tid >> 3;
        const int n0 = tid & 7;
        float2 z[8], y[8];
        const float* r0 = xs + (2 * p) * 64 + n0;
        const float* r1 = xs + (2 * p + 1) * 64 + n0;
#pragma unroll
        for (int n1 = 0; n1 < 8; n1++) z[n1] = make_float2(r0[8 * n1], r1[8 * n1]);
        fft8_(z, y);
        float2* C = (float2*)sB;
#pragma unroll
        for (int k1 = 0; k1 < 8; k1++) {
            int m = n0 * k1;
            C[(p * 8 + k1) * 8 + n0] = cmul_(y[k1], make_float2(ct[m], -st[m]));
        }
    }
    __syncthreads();
    // ---- P1B: FFT8 over n0 -> Z[p][k1+8k2].
    {
        const int p  = tid >> 3;
        const int k1 = tid & 7;
        const float2* C = (const float2*)sB;
        float2 z[8], y[8];
#pragma unroll
        for (int n0 = 0; n0 < 8; n0++) z[n0] = C[(p * 8 + k1) * 8 + n0];
        fft8_(z, y);
        float2* Zs = (float2*)sA;   // xs dead
#pragma unroll
        for (int k2 = 0; k2 < 8; k2++) Zs[p * 64 + k1 + 8 * k2] = y[k2];
    }
    __syncthreads();
    // ---- unpack real-pair spectra into As[row][k], k in [0,32]
    {
        const float2* Zs = (const float2*)sA;
        float2* As = (float2*)sB;   // C dead
        for (int t = tid; t < 1056; t += 256) {
            int p = t / 33, k = t - p * 33;
            float2 Zk = Zs[p * 64 + k];
            float2 Zr = Zs[p * 64 + ((64 - k) & 63)];
            float2 Av = make_float2(0.5f * (Zk.x + Zr.x), 0.5f * (Zk.y - Zr.y));
            float2 Bv = make_float2(0.5f * (Zk.y + Zr.y), 0.5f * (Zr.x - Zk.x));
            As[(2 * p) * 33 + k]     = Av;
            As[(2 * p + 1) * 33 + k] = Bv;
        }
    }
    __syncthreads();
    // ---- P2A: 264 tasks = (col, n0). Column FFT stage 1 + twiddle.
    {
        const float2* As = (const float2*)sB;
        float2* D = (float2*)sA;    // Zs dead
        for (int t = tid; t < 264; t += 256) {
            int col = t >> 3, n0 = t & 7;
            float2 z[8], y[8];
#pragma unroll
            for (int n1 = 0; n1 < 8; n1++) z[n1] = As[(n0 + 8 * n1) * 33 + col];
            fft8_(z, y);
#pragma unroll
            for (int k1 = 0; k1 < 8; k1++) {
                int m = n0 * k1;
                D[(col * 8 + k1) * 8 + n0] = cmul_(y[k1], make_float2(ct[m], -st[m]));
            }
        }
    }
    __syncthreads();
    // ---- P2B: Stage 2 -> |X| accumulate.
    float esum = 0.f;
    {
        const float2* D = (const float2*)sA;
        for (int t = tid; t < 264; t += 256) {
            int col = t >> 3, k1 = t & 7;
            float2 z[8], y[8];
#pragma unroll
            for (int n0 = 0; n0 < 8; n0++) z[n0] = D[(col * 8 + k1) * 8 + n0];
            fft8_(z, y);
            float s = 0.f;
#pragma unroll
            for (int k2 = 0; k2 < 8; k2++) s += sqrtf(y[k2].x * y[k2].x + y[k2].y * y[k2].y);
            esum += (col == 0 || col == 32) ? s : 2.f * s;
        }
    }
#pragma unroll
    for (int o = 16; o; o >>= 1) esum += __shfl_xor_sync(0xffffffffu, esum, o);
    __syncthreads();   // red reuse safe
    if ((tid & 31) == 0) red[tid >> 5] = esum;
    __syncthreads();
    if (tid == 0) {
        float s = 0.f;
#pragma unroll
        for (int i = 0; i < 8; i++) s += red[i];
        g_energy[bc] = s * (1.f / 4096.f);
    }
}

// ==================================================================================
// Kernel 2: FGCA gate pipeline -> per-(b,c) channel scale. One block per batch.
// ==================================================================================
__global__ __launch_bounds__(64) void gates_kernel(
    const float* __restrict__ ex_w, const float* __restrict__ ey_w, const float* __restrict__ ez_w,
    const float* __restrict__ ff_w, const float* __restrict__ ff_b,
    const float* __restrict__ g1_w, const float* __restrict__ g1_b,
    const float* __restrict__ g2_w, const float* __restrict__ g2_b)
{
    const int b = blockIdx.x;
    const int c = threadIdx.x;

    __shared__ float se[64], smn[64], smy[64], smz[64];
    __shared__ float ax[64], ay[64], az[64], af[64], hv[16];

    se[c]  = g_energy[b * 64 + c];
    smn[c] = g_mean[b * 64 + c];
    __syncthreads();

    float e    = se[c];
    int   rank = 0;
#pragma unroll 16
    for (int c2 = 0; c2 < 64; c2++) {
        float e2 = se[c2];
        rank += (e2 > e) || (e2 == e && c2 < c);
    }
    float mask = (rank < 32) ? 1.f : 0.f;
    smy[c] = smn[c] * mask;
    smz[c] = smn[c] * (1.f - mask);
    __syncthreads();

    {
        float w0 = ex_w[0], w1 = ex_w[1], w2 = ex_w[2];
        float v = smn[c] * w1;
        if (c > 0)  v += smn[c - 1] * w0;
        if (c < 63) v += smn[c + 1] * w2;
        ax[c] = sigm_(v);
    }
    {
        float w0 = ey_w[0], w1 = ey_w[1], w2 = ey_w[2];
        float v = smy[c] * w1;
        if (c > 0)  v += smy[c - 1] * w0;
        if (c < 63) v += smy[c + 1] * w2;
        ay[c] = sigm_(v);
    }
    {
        float w0 = ez_w[0], w1 = ez_w[1], w2 = ez_w[2];
        float v = smz[c] * w1;
        if (c > 0)  v += smz[c - 1] * w0;
        if (c < 63) v += smz[c + 1] * w2;
        az[c] = sigm_(v);
    }
    __syncthreads();

    {
        int g = c >> 4;
        const float* src = (g < 2) ? ay : az;
        int base         = (g < 2) ? g * 32 : (g - 2) * 32;
        float s = ff_b[c];
#pragma unroll 8
        for (int j = 0; j < 32; j++) s += ff_w[c * 32 + j] * src[base + j];
        af[c] = s;
    }
    __syncthreads();

    if (c < 16) {
        float hsum = g1_b[c];
#pragma unroll 8
        for (int i = 0; i < 64; i++) hsum += g1_w[c * 128 + i] * af[i];
#pragma unroll 8
        for (int i = 0; i < 64; i++) hsum += g1_w[c * 128 + 64 + i] * ax[i];
        hv[c] = silu_(hsum);
    }
    __syncthreads();

    float gs = g2_b[c];
#pragma unroll
    for (int j = 0; j < 16; j++) gs += g2_w[c * 16 + j] * hv[j];
    float gg = sigm_(gs);

    g_scale[b * 64 + c] = gg * af[c] + (1.f - gg) * ax[c];
}

// ==================================================================================
// Kernel 3: RFA conv + FGCA apply + final 1x1 fuse + BN + SiLU, f32x2-packed,
// channel-team split: 256 threads = 2 teams x 128 px. Team t handles channels
// [t*32, t*32+32) (og groups 2t, 2t+1); partial fused-1x1 accumulators merged
// through smem with add.rn.f32x2. Grid = B*32 = 256 blocks -> 16 warps/SM.
// ==================================================================================
__device__ __forceinline__ void load_nb_(const float* xc, int h, int w0,
                                         bool has_l, bool has_r, float* n)
{
#pragma unroll
    for (int r = 0; r < 3; r++) {
        int   hh = h + r - 1;
        float v0 = 0.f, v1 = 0.f, v2 = 0.f;
        if (hh >= 0 && hh < 64) {
            const float* rowp = xc + hh * 64;
            v1 = rowp[w0];
            if (has_l) v0 = rowp[w0 - 1];
            if (has_r) v2 = rowp[w0 + 1];
        }
        n[r * 3 + 0] = v0; n[r * 3 + 1] = v1; n[r * 3 + 2] = v2;
    }
}

__global__ __launch_bounds__(256) void rfa_fuse_kernel(
    const float* __restrict__ x,
    const float* __restrict__ sc_w, const float* __restrict__ sc_b,
    const float* __restrict__ ac_w, const float* __restrict__ ac_b,
    const float* __restrict__ oc_w, const float* __restrict__ oc_b,
    const float* __restrict__ bng, const float* __restrict__ bnb,
    const float* __restrict__ bnm, const float* __restrict__ bnv,
    const float* __restrict__ fu_w, const float* __restrict__ fu_b,
    const float* __restrict__ fbng, const float* __restrict__ fbnb,
    const float* __restrict__ fbnm, const float* __restrict__ fbnv,
    float* __restrict__ out)
{
    __shared__ __align__(16) float2 s_scw2[3456];   // [(c*9+tap)*6 + jp]
    __shared__ __align__(16) float2 s_scbp[384];
    __shared__ __align__(16) float2 s_acwp[384];
    __shared__ __align__(16) float2 s_acbp[384];
    __shared__ __align__(16) float  s_ocwT[9216];   // [(cl*9+j)*64 + o]
    __shared__ __align__(16) float  s_wsT[4096];    // [cc][o] = fu_w[o][cc]*bnS[o]
    __shared__ __align__(16) float  s_bf[32];
    __shared__ __align__(16) float  s_ob[64], s_bs[64], s_bb[64];
    __shared__ __align__(16) float  s_scale[64], s_s32[32];
    __shared__ __align__(16) u64    s_red[2048];    // [q*128 + pxl] team-1 partials

    const int tid   = threadIdx.x;
    const int b     = blockIdx.x >> 5;
    const int chunk = blockIdx.x & 31;
    const int team  = tid >> 7;          // 0 or 1
    const int pxl   = tid & 127;

    // ---- stage weights
    for (int i = tid; i < 64 * 9 * 5; i += 256) {
        int c2  = i / 45;
        int r   = i - c2 * 45;
        int tap = r / 5;
        int jp  = r - tap * 5;
        int j0  = jp * 2;
        int j1  = (jp == 4) ? 8 : j0 + 1;
        s_scw2[(c2 * 9 + tap) * 6 + jp] =
            make_float2(sc_w[(c2 * 9 + j0) * 9 + tap], sc_w[(c2 * 9 + j1) * 9 + tap]);
    }
    for (int i = tid; i < 64 * 5; i += 256) {
        int c2 = i / 5, jp = i - c2 * 5;
        int j0 = jp * 2;
        int j1 = (jp == 4) ? 8 : j0 + 1;
        s_scbp[c2 * 6 + jp] = make_float2(sc_b[c2 * 9 + j0], sc_b[c2 * 9 + j1]);
        s_acwp[c2 * 6 + jp] = make_float2(ac_w[c2 * 9 + j0], ac_w[c2 * 9 + j1]);
        s_acbp[c2 * 6 + jp] = make_float2(ac_b[c2 * 9 + j0], ac_b[c2 * 9 + j1]);
    }
    for (int i = tid; i < 9216; i += 256) {
        int o = i / 144, r = i - o * 144;
        int cl = r / 9,  j = r - cl * 9;
        s_ocwT[(cl * 9 + j) * 64 + o] = oc_w[i];
    }
    if (tid < 64) {
        float s = bng[tid] * rsqrtf(bnv[tid] + 1e-5f);
        s_bs[tid]    = s;
        s_bb[tid]    = bnb[tid] - bnm[tid] * s;
        s_ob[tid]    = oc_b[tid];
        s_scale[tid] = g_scale[b * 64 + tid];
    }
    if (tid < 32) {
        float s = fbng[tid] * rsqrtf(fbnv[tid] + 1e-5f);
        s_s32[tid] = s;
        s_bf[tid]  = fu_b[tid] * s + fbnb[tid] - fbnm[tid] * s;
    }
    __syncthreads();
    for (int i = tid; i < 4096; i += 256) {
        int o = i & 31, cc = i >> 5;
        s_wsT[i] = fu_w[o * 128 + cc] * s_s32[o];
    }
    __syncthreads();

    const int pix = chunk * 128 + pxl;
    const int h   = pix >> 6;
    const int w0  = pix & 63;
    const float* xb = x + (size_t)b * CC * NPIX;
    const bool has_l = (w0 > 0);
    const bool has_r = (w0 < 63);
    const int cbase  = team * 32;

    // fused 1x1 accumulators: pairs of adjacent output channels; team 1 from zero
    u64 fp[16];
#pragma unroll
    for (int q = 0; q < 16; q++) fp[q] = team ? 0ull : *(const u64*)&s_bf[q * 2];

    // software pipeline: preload first channel of this team
    float ncur[9], nnext[9];
    load_nb_(xb + (size_t)cbase * NPIX, h, w0, has_l, has_r, ncur);

    for (int ogl = 0; ogl < 2; ogl++) {
        const int og = team * 2 + ogl;
        u64 ap[8];
#pragma unroll
        for (int q = 0; q < 8; q++) ap[q] = *(const u64*)&s_ob[og * 16 + q * 2];

#pragma unroll 2
        for (int cl = 0; cl < 16; cl++) {
            const int c = og * 16 + cl;
            if (c < cbase + 31) load_nb_(xb + (size_t)(c + 1) * NPIX, h, w0, has_l, has_r, nnext);

            float p = ((((ncur[0] + ncur[1]) + (ncur[2] + ncur[3])) +
                        ((ncur[5] + ncur[6]) + (ncur[7] + ncur[8]))) + ncur[4]) * (1.f / 9.f);

            // softmax numerators (shift-invariant, bounded logits -> no max sub);
            // exps issued before the dw-conv fma block to hide MUFU latency
            float e[9];
            {
                u64 pp = pack1_(p);
                const u64* wq = (const u64*)&s_acwp[c * 6];
                const u64* bq = (const u64*)&s_acbp[c * 6];
                float a0, a1, dum;
                u64 lg;
                lg = fma2_(pp, wq[0], bq[0]); unpack2_(lg, a0, a1); e[0] = __expf(a0); e[1] = __expf(a1);
                lg = fma2_(pp, wq[1], bq[1]); unpack2_(lg, a0, a1); e[2] = __expf(a0); e[3] = __expf(a1);
                lg = fma2_(pp, wq[2], bq[2]); unpack2_(lg, a0, a1); e[4] = __expf(a0); e[5] = __expf(a1);
                lg = fma2_(pp, wq[3], bq[3]); unpack2_(lg, a0, a1); e[6] = __expf(a0); e[7] = __expf(a1);
                lg = fma2_(pp, wq[4], bq[4]); unpack2_(lg, a0, dum); e[8] = __expf(a0);
            }
            float sum = ((((e[0] + e[1]) + (e[2] + e[3])) +
                          ((e[4] + e[5]) + (e[6] + e[7]))) + e[8]);
            float rs = __fdividef(1.f, sum);

            // dw conv over taps, RF positions packed in pairs
            u64 dp[5];
            {
                const u64* bq = (const u64*)&s_scbp[c * 6];
#pragma unroll
                for (int jp = 0; jp < 5; jp++) dp[jp] = bq[jp];
            }
#pragma unroll
            for (int tap = 0; tap < 9; tap++) {
                u64 nv = pack1_(ncur[tap]);
                const u64* wp = (const u64*)&s_scw2[(c * 9 + tap) * 6];
                ulonglong2 w01 = ((const ulonglong2*)wp)[0];
                ulonglong2 w23 = ((const ulonglong2*)wp)[1];
                u64        w4  = wp[4];
                dp[0] = fma2_(nv, w01.x, dp[0]);
                dp[1] = fma2_(nv, w01.y, dp[1]);
                dp[2] = fma2_(nv, w23.x, dp[2]);
                dp[3] = fma2_(nv, w23.y, dp[3]);
                dp[4] = fma2_(nv, w4,    dp[4]);
            }

            float t[9];
            {
                float d[10];
#pragma unroll
                for (int jp = 0; jp < 5; jp++) unpack2_(dp[jp], d[2 * jp], d[2 * jp + 1]);
#pragma unroll
                for (int j = 0; j < 9; j++) t[j] = silu_(d[j]) * e[j];
            }

            // grouped projection over output pairs
#pragma unroll
            for (int j = 0; j < 9; j++) {
                u64 tpj = pack1_(t[j] * rs);
                const ulonglong2* op = (const ulonglong2*)&s_ocwT[(cl * 9 + j) * 64 + og * 16];
                ulonglong2 w01 = op[0], w23 = op[1], w45 = op[2], w67 = op[3];
                ap[0] = fma2_(w01.x, tpj, ap[0]);
                ap[1] = fma2_(w01.y, tpj, ap[1]);
                ap[2] = fma2_(w23.x, tpj, ap[2]);
                ap[3] = fma2_(w23.y, tpj, ap[3]);
                ap[4] = fma2_(w45.x, tpj, ap[4]);
                ap[5] = fma2_(w45.y, tpj, ap[5]);
                ap[6] = fma2_(w67.x, tpj, ap[6]);
                ap[7] = fma2_(w67.y, tpj, ap[7]);
            }

            // fused 1x1: x_fgca contribution (x center * channel scale)
            u64 xp = pack1_(ncur[4] * s_scale[c]);
            const ulonglong2* wx = (const ulonglong2*)&s_wsT[(64 + c) * 32];
#pragma unroll
            for (int q = 0; q < 8; q++) {
                ulonglong2 wv = wx[q];
                fp[q * 2 + 0] = fma2_(wv.x, xp, fp[q * 2 + 0]);
                fp[q * 2 + 1] = fma2_(wv.y, xp, fp[q * 2 + 1]);
            }

            // rotate pipeline registers
#pragma unroll
            for (int q = 0; q < 9; q++) ncur[q] = nnext[q];
        }

        // BN + SiLU on rfa outputs, then fused-1x1 x_rfa contribution
#pragma unroll
        for (int q = 0; q < 8; q++) {
            int o = og * 16 + q * 2;
            u64 bsp = *(const u64*)&s_bs[o];
            u64 bbp = *(const u64*)&s_bb[o];
            u64 z = fma2_(ap[q], bsp, bbp);
            float ya, yb;
            unpack2_(z, ya, yb);
            u64 pya = pack1_(silu_(ya));
            u64 pyb = pack1_(silu_(yb));
            const ulonglong2* w0p = (const ulonglong2*)&s_wsT[o * 32];
            const ulonglong2* w1p = (const ulonglong2*)&s_wsT[(o + 1) * 32];
#pragma unroll
            for (int q2 = 0; q2 < 8; q2++) {
                ulonglong2 wa = w0p[q2];
                ulonglong2 wb = w1p[q2];
                fp[q2 * 2 + 0] = fma2_(wa.x, pya, fp[q2 * 2 + 0]);
                fp[q2 * 2 + 1] = fma2_(wa.y, pya, fp[q2 * 2 + 1]);
                fp[q2 * 2 + 0] = fma2_(wb.x, pyb, fp[q2 * 2 + 0]);
                fp[q2 * 2 + 1] = fma2_(wb.y, pyb, fp[q2 * 2 + 1]);
            }
        }
    }

    // ---- cross-team reduction: team 1 publishes, team 0 merges + stores
    if (team == 1) {
#pragma unroll
        for (int q = 0; q < 16; q++) s_red[q * 128 + pxl] = fp[q];
    }
    __syncthreads();
    if (team == 0) {
        float* outp = out + (size_t)(b * 32) * NPIX + pix;
#pragma unroll
        for (int q = 0; q < 16; q++) {
            u64 tot = add2_(fp[q], s_red[q * 128 + pxl]);
            float ea, eb;
            unpack2_(tot, ea, eb);
            outp[(size_t)(2 * q + 0) * NPIX] = silu_(ea);
            outp[(size_t)(2 * q + 1) * NPIX] = silu_(eb);
        }
    }
}

// ==================================================================================
extern "C" void kernel_launch(void* const* d_in, const int* in_sizes, int n_in,
                              void* d_out, int out_size)
{
    const float* x      = (const float*)d_in[0];
    const float* sc_w   = (const float*)d_in[1];
    const float* sc_b   = (const float*)d_in[2];
    const float* ac_w   = (const float*)d_in[3];
    const float* ac_b   = (const float*)d_in[4];
    const float* oc_w   = (const float*)d_in[5];
    const float* oc_b   = (const float*)d_in[6];
    const float* oc_bng = (const float*)d_in[7];
    const float* oc_bnb = (const float*)d_in[8];
    const float* oc_bnm = (const float*)d_in[9];
    const float* oc_bnv = (const float*)d_in[10];
    const float* ex_w   = (const float*)d_in[11];
    const float* ey_w   = (const float*)d_in[12];
    const float* ez_w   = (const float*)d_in[13];
    const float* ff_w   = (const float*)d_in[14];
    const float* ff_b   = (const float*)d_in[15];
    const float* g1_w   = (const float*)d_in[16];
    const float* g1_b   = (const float*)d_in[17];
    const float* g2_w   = (const float*)d_in[18];
    const float* g2_b   = (const float*)d_in[19];
    const float* fu_w   = (const float*)d_in[20];
    const float* fu_b   = (const float*)d_in[21];
    const float* fu_bng = (const float*)d_in[22];
    const float* fu_bnb = (const float*)d_in[23];
    const float* fu_bnm = (const float*)d_in[24];
    const float* fu_bnv = (const float*)d_in[25];

    fft_energy_kernel<<<BB * CC, 256>>>(x);
    gates_kernel<<<BB, 64>>>(ex_w, ey_w, ez_w, ff_w, ff_b, g1_w, g1_b, g2_w, g2_b);
    rfa_fuse_kernel<<<BB * 32, 256>>>(x, sc_w, sc_b, ac_w, ac_b, oc_w, oc_b,
                                      oc_bng, oc_bnb, oc_bnm, oc_bnv,
                                      fu_w, fu_b, fu_bng, fu_bnb, fu_bnm, fu_bnv,
                                      (float*)d_out);
}

// round 15
// speedup vs baseline: 1.2313x; 1.2313x over previous
#include <cuda_runtime.h>
#include <math.h>

#define BB   8
#define CC   64
#define NPIX 4096   // 64*64

typedef unsigned long long u64;

// ---------------- scratch (static device globals; no allocation) ----------------
__device__ float g_mean[BB * CC];
__device__ float g_energy[BB * CC];
__device__ float g_scale[BB * CC];
__device__ __align__(16) float g_pack[23040];   // pre-packed weights, rfa smem image

// pack layout offsets (floats)
#define OFF_SCW2  0        // 6912: float2[(c*9+tap)*6+jp] dw weight pairs (jp<5)
#define OFF_SCBP  6912     // 768:  float2[c*6+jp] dw bias pairs
#define OFF_ACWP  7680     // 768:  float2[c*6+jp] att weight pairs
#define OFF_ACBP  8448     // 768:  float2[c*6+jp] att bias pairs
#define OFF_OCWT  9216     // 9216: [(cl*9+j)*64 + o] transposed projection
#define OFF_WST   18432    // 4096: [cc*32 + o] = fu_w[o][cc]*bnS[o]
#define OFF_BF    22528    // 32
#define OFF_OB    22560    // 64
#define OFF_BS    22624    // 64
#define OFF_BB    22688    // 64
// [22752, 23040) zero padding
#define SM_SCALE  23040    // +64 in smem only
#define SM_TOTAL  23104

__device__ __forceinline__ float sigm_(float v) { return __fdividef(1.f, 1.f + __expf(-v)); }
__device__ __forceinline__ float silu_(float v) { return v * __fdividef(1.f, 1.f + __expf(-v)); }

// ---------------- packed fp32x2 helpers (FFMA2 path, sm_100+) ----------------
__device__ __forceinline__ u64 pack2_(float lo, float hi) {
    u64 r; asm("mov.b64 %0, {%1, %2};" : "=l"(r) : "f"(lo), "f"(hi)); return r;
}
__device__ __forceinline__ u64 pack1_(float v) {
    u64 r; asm("mov.b64 %0, {%1, %1};" : "=l"(r) : "f"(v)); return r;
}
__device__ __forceinline__ void unpack2_(u64 p, float& lo, float& hi) {
    asm("mov.b64 {%0, %1}, %2;" : "=f"(lo), "=f"(hi) : "l"(p));
}
__device__ __forceinline__ u64 fma2_(u64 a, u64 b, u64 c) {
    u64 d; asm("fma.rn.f32x2 %0, %1, %2, %3;" : "=l"(d) : "l"(a), "l"(b), "l"(c)); return d;
}

// ---------------- complex helpers (forward convention e^{-2pi i}) ----------------
__device__ __forceinline__ float2 cadd_(float2 a, float2 b) { return make_float2(a.x + b.x, a.y + b.y); }
__device__ __forceinline__ float2 csub_(float2 a, float2 b) { return make_float2(a.x - b.x, a.y - b.y); }
__device__ __forceinline__ float2 cmul_(float2 a, float2 b) {
    return make_float2(a.x * b.x - a.y * b.y, a.x * b.y + a.y * b.x);
}
__device__ __forceinline__ float2 cmni_(float2 a) { return make_float2(a.y, -a.x); }   // a * (-i)

__device__ __forceinline__ void fft8_(const float2* z, float2* y)
{
    const float Cq = 0.70710678118654752f;
    float2 t0 = cadd_(z[0], z[4]), t1 = csub_(z[0], z[4]);
    float2 t2 = cadd_(z[2], z[6]), t3 = csub_(z[2], z[6]);
    float2 E0 = cadd_(t0, t2), E2 = csub_(t0, t2);
    float2 it3 = cmni_(t3);
    float2 E1 = cadd_(t1, it3), E3 = csub_(t1, it3);
    float2 u0 = cadd_(z[1], z[5]), u1 = csub_(z[1], z[5]);
    float2 u2 = cadd_(z[3], z[7]), u3 = csub_(z[3], z[7]);
    float2 O0 = cadd_(u0, u2), O2 = csub_(u0, u2);
    float2 iu3 = cmni_(u3);
    float2 O1 = cadd_(u1, iu3), O3 = csub_(u1, iu3);
    float2 W1O1 = make_float2(Cq * (O1.x + O1.y), Cq * (O1.y - O1.x));
    float2 W2O2 = cmni_(O2);
    float2 W3O3 = make_float2(Cq * (O3.y - O3.x), -Cq * (O3.x + O3.y));
    y[0] = cadd_(E0, O0);   y[4] = csub_(E0, O0);
    y[1] = cadd_(E1, W1O1); y[5] = csub_(E1, W1O1);
    y[2] = cadd_(E2, W2O2); y[6] = csub_(E2, W2O2);
    y[3] = cadd_(E3, W3O3); y[7] = csub_(E3, W3O3);
}

// ==================================================================================
// Kernel 0: pre-pack weights into g_pack (rfa smem image). 90 blocks x 256 thr.
// ==================================================================================
__global__ __launch_bounds__(256) void pack_kernel(
    const float* __restrict__ sc_w, const float* __restrict__ sc_b,
    const float* __restrict__ ac_w, const float* __restrict__ ac_b,
    const float* __restrict__ oc_w, const float* __restrict__ oc_b,
    const float* __restrict__ bng, const float* __restrict__ bnb,
    const float* __restrict__ bnm, const float* __restrict__ bnv,
    const float* __restrict__ fu_w, const float* __restrict__ fu_b,
    const float* __restrict__ fbng, const float* __restrict__ fbnb,
    const float* __restrict__ fbnm, const float* __restrict__ fbnv)
{
    int i = blockIdx.x * 256 + threadIdx.x;
    if (i >= 23040) return;
    float v = 0.f;
    if (i < 6912) {                         // scw2 pairs
        int pairIdx = i >> 1, half = i & 1;
        int g = pairIdx / 6, jp = pairIdx - (pairIdx / 6) * 6;
        int c = g / 9, tap = g - c * 9;
        if (jp < 5) {
            int j = (jp == 4) ? 8 : jp * 2 + half;
            v = sc_w[(c * 9 + j) * 9 + tap];
        }
    } else if (i < 7680) {                  // scbp pairs
        int r = i - 6912;
        int pairIdx = r >> 1, half = r & 1;
        int c = pairIdx / 6, jp = pairIdx - c * 6;
        if (jp < 5) { int j = (jp == 4) ? 8 : jp * 2 + half; v = sc_b[c * 9 + j]; }
    } else if (i < 8448) {                  // acwp pairs
        int r = i - 7680;
        int pairIdx = r >> 1, half = r & 1;
        int c = pairIdx / 6, jp = pairIdx - c * 6;
        if (jp < 5) { int j = (jp == 4) ? 8 : jp * 2 + half; v = ac_w[c * 9 + j]; }
    } else if (i < 9216) {                  // acbp pairs
        int r = i - 8448;
        int pairIdx = r >> 1, half = r & 1;
        int c = pairIdx / 6, jp = pairIdx - c * 6;
        if (jp < 5) { int j = (jp == 4) ? 8 : jp * 2 + half; v = ac_b[c * 9 + j]; }
    } else if (i < 18432) {                 // ocwT transpose
        int r = i - 9216;
        int grp = r >> 6, o = r & 63;       // grp = cl*9+j
        int cl = grp / 9, j = grp - cl * 9;
        v = oc_w[o * 144 + cl * 9 + j];
    } else if (i < 22528) {                 // wsT (BN-folded fuse weights)
        int r = i - 18432;
        int cc = r >> 5, o = r & 31;
        float s = fbng[o] * rsqrtf(fbnv[o] + 1e-5f);
        v = fu_w[o * 128 + cc] * s;
    } else if (i < 22560) {                 // bf
        int o = i - 22528;
        float s = fbng[o] * rsqrtf(fbnv[o] + 1e-5f);
        v = fu_b[o] * s + fbnb[o] - fbnm[o] * s;
    } else if (i < 22624) {                 // ob
        v = oc_b[i - 22560];
    } else if (i < 22688) {                 // bs
        int o = i - 22624;
        v = bng[o] * rsqrtf(bnv[o] + 1e-5f);
    } else if (i < 22752) {                 // bb
        int o = i - 22688;
        float s = bng[o] * rsqrtf(bnv[o] + 1e-5f);
        v = bnb[o] - bnm[o] * s;
    }                                       // else padding stays 0
    g_pack[i] = v;
}

// ==================================================================================
// Kernel 1: per-(b,c) 64x64 FFT2 magnitude mean + spatial mean, radix-8 FFT.
// ==================================================================================
__global__ __launch_bounds__(256) void fft_energy_kernel(const float* __restrict__ x)
{
    __shared__ __align__(16) float sA[4352];   // xs -> Zs -> D
    __shared__ __align__(16) float sB[4352];   // C  -> As
    __shared__ float ct[64], st[64];
    __shared__ float red[8];

    const int tid = threadIdx.x;
    const int bc  = blockIdx.x;

    if (tid < 64) {
        float sv, cv;
        sincosf(0.09817477042468103f * (float)tid, &sv, &cv);   // 2*pi/64 * tid
        ct[tid] = cv;
        st[tid] = sv;
    }

    float* xs = sA;
    const float* xp = x + (size_t)bc * NPIX;
    float lsum = 0.f;
    for (int i = tid; i < 4096; i += 256) {
        float v = xp[i];
        xs[i] = v;
        lsum += v;
    }
#pragma unroll
    for (int o = 16; o; o >>= 1) lsum += __shfl_xor_sync(0xffffffffu, lsum, o);
    if ((tid & 31) == 0) red[tid >> 5] = lsum;
    __syncthreads();
    if (tid == 0) {
        float s = 0.f;
#pragma unroll
        for (int i = 0; i < 8; i++) s += red[i];
        g_mean[bc] = s * (1.f / 4096.f);
    }

    // ---- P1A
    {
        const int p  = tid >> 3;
        const int n0 = tid & 7;
        float2 z[8], y[8];
        const float* r0 = xs + (2 * p) * 64 + n0;
        const float* r1 = xs + (2 * p + 1) * 64 + n0;
#pragma unroll
        for (int n1 = 0; n1 < 8; n1++) z[n1] = make_float2(r0[8 * n1], r1[8 * n1]);
        fft8_(z, y);
        float2* C = (float2*)sB;
#pragma unroll
        for (int k1 = 0; k1 < 8; k1++) {
            int m = n0 * k1;
            C[(p * 8 + k1) * 8 + n0] = cmul_(y[k1], make_float2(ct[m], -st[m]));
        }
    }
    __syncthreads();
    // ---- P1B
    {
        const int p  = tid >> 3;
        const int k1 = tid & 7;
        const float2* C = (const float2*)sB;
        float2 z[8], y[8];
#pragma unroll
        for (int n0 = 0; n0 < 8; n0++) z[n0] = C[(p * 8 + k1) * 8 + n0];
        fft8_(z, y);
        float2* Zs = (float2*)sA;   // xs dead
#pragma unroll
        for (int k2 = 0; k2 < 8; k2++) Zs[p * 64 + k1 + 8 * k2] = y[k2];
    }
    __syncthreads();
    // ---- unpack
    {
        const float2* Zs = (const float2*)sA;
        float2* As = (float2*)sB;   // C dead
        for (int t = tid; t < 1056; t += 256) {
            int p = t / 33, k = t - p * 33;
            float2 Zk = Zs[p * 64 + k];
            float2 Zr = Zs[p * 64 + ((64 - k) & 63)];
            float2 Av = make_float2(0.5f * (Zk.x + Zr.x), 0.5f * (Zk.y - Zr.y));
            float2 Bv = make_float2(0.5f * (Zk.y + Zr.y), 0.5f * (Zr.x - Zk.x));
            As[(2 * p) * 33 + k]     = Av;
            As[(2 * p + 1) * 33 + k] = Bv;
        }
    }
    __syncthreads();
    // ---- P2A
    {
        const float2* As = (const float2*)sB;
        float2* D = (float2*)sA;    // Zs dead
        for (int t = tid; t < 264; t += 256) {
            int col = t >> 3, n0 = t & 7;
            float2 z[8], y[8];
#pragma unroll
            for (int n1 = 0; n1 < 8; n1++) z[n1] = As[(n0 + 8 * n1) * 33 + col];
            fft8_(z, y);
#pragma unroll
            for (int k1 = 0; k1 < 8; k1++) {
                int m = n0 * k1;
                D[(col * 8 + k1) * 8 + n0] = cmul_(y[k1], make_float2(ct[m], -st[m]));
            }
        }
    }
    __syncthreads();
    // ---- P2B
    float esum = 0.f;
    {
        const float2* D = (const float2*)sA;
        for (int t = tid; t < 264; t += 256) {
            int col = t >> 3, k1 = t & 7;
            float2 z[8], y[8];
#pragma unroll
            for (int n0 = 0; n0 < 8; n0++) z[n0] = D[(col * 8 + k1) * 8 + n0];
            fft8_(z, y);
            float s = 0.f;
#pragma unroll
            for (int k2 = 0; k2 < 8; k2++) s += sqrtf(y[k2].x * y[k2].x + y[k2].y * y[k2].y);
            esum += (col == 0 || col == 32) ? s : 2.f * s;
        }
    }
#pragma unroll
    for (int o = 16; o; o >>= 1) esum += __shfl_xor_sync(0xffffffffu, esum, o);
    __syncthreads();
    if ((tid & 31) == 0) red[tid >> 5] = esum;
    __syncthreads();
    if (tid == 0) {
        float s = 0.f;
#pragma unroll
        for (int i = 0; i < 8; i++) s += red[i];
        g_energy[bc] = s * (1.f / 4096.f);
    }
}

// ==================================================================================
// Kernel 2: FGCA gate pipeline -> per-(b,c) channel scale. One block per batch.
// ==================================================================================
__global__ __launch_bounds__(64) void gates_kernel(
    const float* __restrict__ ex_w, const float* __restrict__ ey_w, const float* __restrict__ ez_w,
    const float* __restrict__ ff_w, const float* __restrict__ ff_b,
    const float* __restrict__ g1_w, const float* __restrict__ g1_b,
    const float* __restrict__ g2_w, const float* __restrict__ g2_b)
{
    const int b = blockIdx.x;
    const int c = threadIdx.x;

    __shared__ float se[64], smn[64], smy[64], smz[64];
    __shared__ float ax[64], ay[64], az[64], af[64], hv[16];

    se[c]  = g_energy[b * 64 + c];
    smn[c] = g_mean[b * 64 + c];
    __syncthreads();

    float e    = se[c];
    int   rank = 0;
#pragma unroll 16
    for (int c2 = 0; c2 < 64; c2++) {
        float e2 = se[c2];
        rank += (e2 > e) || (e2 == e && c2 < c);
    }
    float mask = (rank < 32) ? 1.f : 0.f;
    smy[c] = smn[c] * mask;
    smz[c] = smn[c] * (1.f - mask);
    __syncthreads();

    {
        float w0 = ex_w[0], w1 = ex_w[1], w2 = ex_w[2];
        float v = smn[c] * w1;
        if (c > 0)  v += smn[c - 1] * w0;
        if (c < 63) v += smn[c + 1] * w2;
        ax[c] = sigm_(v);
    }
    {
        float w0 = ey_w[0], w1 = ey_w[1], w2 = ey_w[2];
        float v = smy[c] * w1;
        if (c > 0)  v += smy[c - 1] * w0;
        if (c < 63) v += smy[c + 1] * w2;
        ay[c] = sigm_(v);
    }
    {
        float w0 = ez_w[0], w1 = ez_w[1], w2 = ez_w[2];
        float v = smz[c] * w1;
        if (c > 0)  v += smz[c - 1] * w0;
        if (c < 63) v += smz[c + 1] * w2;
        az[c] = sigm_(v);
    }
    __syncthreads();

    {
        int g = c >> 4;
        const float* src = (g < 2) ? ay : az;
        int base         = (g < 2) ? g * 32 : (g - 2) * 32;
        float s = ff_b[c];
#pragma unroll 8
        for (int j = 0; j < 32; j++) s += ff_w[c * 32 + j] * src[base + j];
        af[c] = s;
    }
    __syncthreads();

    if (c < 16) {
        float hsum = g1_b[c];
#pragma unroll 8
        for (int i = 0; i < 64; i++) hsum += g1_w[c * 128 + i] * af[i];
#pragma unroll 8
        for (int i = 0; i < 64; i++) hsum += g1_w[c * 128 + 64 + i] * ax[i];
        hv[c] = silu_(hsum);
    }
    __syncthreads();

    float gs = g2_b[c];
#pragma unroll
    for (int j = 0; j < 16; j++) gs += g2_w[c * 16 + j] * hv[j];
    float gg = sigm_(gs);

    g_scale[b * 64 + c] = gg * af[c] + (1.f - gg) * ax[c];
}

// ==================================================================================
// Kernel 3: RFA conv + FGCA apply + final 1x1 fuse + BN + SiLU, f32x2-packed.
// 128 threads/block, 1 px/thread, all 64 channels per thread. Grid = B*32 = 256
// blocks -> 2 blocks/SM on all 148 SMs. Weight staging = vectorized copy of
// the pre-packed g_pack image (45 float4 iterations).
// ==================================================================================
__device__ __forceinline__ void load_nb_(const float* xc, int h, int w0,
                                         bool has_l, bool has_r, float* n)
{
#pragma unroll
    for (int r = 0; r < 3; r++) {
        int   hh = h + r - 1;
        float v0 = 0.f, v1 = 0.f, v2 = 0.f;
        if (hh >= 0 && hh < 64) {
            const float* rowp = xc + hh * 64;
            v1 = rowp[w0];
            if (has_l) v0 = rowp[w0 - 1];
            if (has_r) v2 = rowp[w0 + 1];
        }
        n[r * 3 + 0] = v0; n[r * 3 + 1] = v1; n[r * 3 + 2] = v2;
    }
}

__global__ __launch_bounds__(128) void rfa_fuse_kernel(
    const float* __restrict__ x, float* __restrict__ out)
{
    __shared__ __align__(16) float sm[SM_TOTAL];

    const int tid   = threadIdx.x;
    const int b     = blockIdx.x >> 5;
    const int chunk = blockIdx.x & 31;

    // ---- staging: straight vectorized copy of the packed image
    {
        const float4* src = (const float4*)g_pack;
        float4* dst = (float4*)sm;
#pragma unroll 5
        for (int i = tid; i < 5760; i += 128) dst[i] = src[i];
        if (tid < 64) sm[SM_SCALE + tid] = g_scale[b * 64 + tid];
    }
    __syncthreads();

    const int pix = chunk * 128 + tid;
    const int h   = pix >> 6;
    const int w0  = pix & 63;
    const float* xb = x + (size_t)b * CC * NPIX;
    const bool has_l = (w0 > 0);
    const bool has_r = (w0 < 63);

    // fused 1x1 accumulators: pairs of adjacent output channels
    u64 fp[16];
#pragma unroll
    for (int q = 0; q < 16; q++) fp[q] = *(const u64*)&sm[OFF_BF + q * 2];

    // software pipeline: preload channel 0 neighborhood
    float ncur[9], nnext[9];
    load_nb_(xb, h, w0, has_l, has_r, ncur);

    for (int og = 0; og < 4; og++) {
        u64 ap[8];
#pragma unroll
        for (int q = 0; q < 8; q++) ap[q] = *(const u64*)&sm[OFF_OB + og * 16 + q * 2];

#pragma unroll 2
        for (int cl = 0; cl < 16; cl++) {
            const int c = og * 16 + cl;
            if (c < 63) load_nb_(xb + (size_t)(c + 1) * NPIX, h, w0, has_l, has_r, nnext);

            float p = ((((ncur[0] + ncur[1]) + (ncur[2] + ncur[3])) +
                        ((ncur[5] + ncur[6]) + (ncur[7] + ncur[8]))) + ncur[4]) * (1.f / 9.f);

            // softmax numerators (shift-invariant; bounded logits -> no max sub);
            // exps issued before the dw-conv fma block to hide MUFU latency
            float e[9];
            {
                u64 pp = pack1_(p);
                const u64* wq = (const u64*)&sm[OFF_ACWP + c * 12];
                const u64* bq = (const u64*)&sm[OFF_ACBP + c * 12];
                float a0, a1, dum;
                u64 lg;
                lg = fma2_(pp, wq[0], bq[0]); unpack2_(lg, a0, a1); e[0] = __expf(a0); e[1] = __expf(a1);
                lg = fma2_(pp, wq[1], bq[1]); unpack2_(lg, a0, a1); e[2] = __expf(a0); e[3] = __expf(a1);
                lg = fma2_(pp, wq[2], bq[2]); unpack2_(lg, a0, a1); e[4] = __expf(a0); e[5] = __expf(a1);
                lg = fma2_(pp, wq[3], bq[3]); unpack2_(lg, a0, a1); e[6] = __expf(a0); e[7] = __expf(a1);
                lg = fma2_(pp, wq[4], bq[4]); unpack2_(lg, a0, dum); e[8] = __expf(a0);
            }
            float sum = ((((e[0] + e[1]) + (e[2] + e[3])) +
                          ((e[4] + e[5]) + (e[6] + e[7]))) + e[8]);
            float rs = __fdividef(1.f, sum);

            // dw conv over taps, RF positions packed in pairs
            u64 dp[5];
            {
                const u64* bq = (const u64*)&sm[OFF_SCBP + c * 12];
#pragma unroll
                for (int jp = 0; jp < 5; jp++) dp[jp] = bq[jp];
            }
#pragma unroll
            for (int tap = 0; tap < 9; tap++) {
                u64 nv = pack1_(ncur[tap]);
                const u64* wp = (const u64*)&sm[OFF_SCW2 + (c * 9 + tap) * 12];
                ulonglong2 w01 = ((const ulonglong2*)wp)[0];
                ulonglong2 w23 = ((const ulonglong2*)wp)[1];
                u64        w4  = wp[4];
                dp[0] = fma2_(nv, w01.x, dp[0]);
                dp[1] = fma2_(nv, w01.y, dp[1]);
                dp[2] = fma2_(nv, w23.x, dp[2]);
                dp[3] = fma2_(nv, w23.y, dp[3]);
                dp[4] = fma2_(nv, w4,    dp[4]);
            }

            float t[9];
            {
                float d[10];
#pragma unroll
                for (int jp = 0; jp < 5; jp++) unpack2_(dp[jp], d[2 * jp], d[2 * jp + 1]);
#pragma unroll
                for (int j = 0; j < 9; j++) t[j] = silu_(d[j]) * e[j];
            }

            // grouped projection over output pairs
#pragma unroll
            for (int j = 0; j < 9; j++) {
                u64 tpj = pack1_(t[j] * rs);
                const ulonglong2* op = (const ulonglong2*)&sm[OFF_OCWT + (cl * 9 + j) * 64 + og * 16];
                ulonglong2 w01 = op[0], w23 = op[1], w45 = op[2], w67 = op[3];
                ap[0] = fma2_(w01.x, tpj, ap[0]);
                ap[1] = fma2_(w01.y, tpj, ap[1]);
                ap[2] = fma2_(w23.x, tpj, ap[2]);
                ap[3] = fma2_(w23.y, tpj, ap[3]);
                ap[4] = fma2_(w45.x, tpj, ap[4]);
                ap[5] = fma2_(w45.y, tpj, ap[5]);
                ap[6] = fma2_(w67.x, tpj, ap[6]);
                ap[7] = fma2_(w67.y, tpj, ap[7]);
            }

            // fused 1x1: x_fgca contribution (x center * channel scale)
            u64 xp = pack1_(ncur[4] * sm[SM_SCALE + c]);
            const ulonglong2* wx = (const ulonglong2*)&sm[OFF_WST + (64 + c) * 32];
#pragma unroll
            for (int q = 0; q < 8; q++) {
                ulonglong2 wv = wx[q];
                fp[q * 2 + 0] = fma2_(wv.x, xp, fp[q * 2 + 0]);
                fp[q * 2 + 1] = fma2_(wv.y, xp, fp[q * 2 + 1]);
            }

            // rotate pipeline registers
#pragma unroll
            for (int q = 0; q < 9; q++) ncur[q] = nnext[q];
        }

        // BN + SiLU on rfa outputs, then fused-1x1 x_rfa contribution
#pragma unroll
        for (int q = 0; q < 8; q++) {
            int o = og * 16 + q * 2;
            u64 bsp = *(const u64*)&sm[OFF_BS + o];
            u64 bbp = *(const u64*)&sm[OFF_BB + o];
            u64 z = fma2_(ap[q], bsp, bbp);
            float ya, yb;
            unpack2_(z, ya, yb);
            u64 pya = pack1_(silu_(ya));
            u64 pyb = pack1_(silu_(yb));
            const ulonglong2* w0p = (const ulonglong2*)&sm[OFF_WST + o * 32];
            const ulonglong2* w1p = (const ulonglong2*)&sm[OFF_WST + (o + 1) * 32];
#pragma unroll
            for (int q2 = 0; q2 < 8; q2++) {
                ulonglong2 wa = w0p[q2];
                ulonglong2 wb = w1p[q2];
                fp[q2 * 2 + 0] = fma2_(wa.x, pya, fp[q2 * 2 + 0]);
                fp[q2 * 2 + 1] = fma2_(wa.y, pya, fp[q2 * 2 + 1]);
                fp[q2 * 2 + 0] = fma2_(wb.x, pyb, fp[q2 * 2 + 0]);
                fp[q2 * 2 + 1] = fma2_(wb.y, pyb, fp[q2 * 2 + 1]);
            }
        }
    }

    // epilogue: SiLU + store 32 output channels
    float* outp = out + (size_t)(b * 32) * NPIX + pix;
#pragma unroll
    for (int q = 0; q < 16; q++) {
        float ea, eb;
        unpack2_(fp[q], ea, eb);
        outp[(size_t)(2 * q + 0) * NPIX] = silu_(ea);
        outp[(size_t)(2 * q + 1) * NPIX] = silu_(eb);
    }
}

// ==================================================================================
extern "C" void kernel_launch(void* const* d_in, const int* in_sizes, int n_in,
                              void* d_out, int out_size)
{
    const float* x      = (const float*)d_in[0];
    const float* sc_w   = (const float*)d_in[1];
    const float* sc_b   = (const float*)d_in[2];
    const float* ac_w   = (const float*)d_in[3];
    const float* ac_b   = (const float*)d_in[4];
    const float* oc_w   = (const float*)d_in[5];
    const float* oc_b   = (const float*)d_in[6];
    const float* oc_bng = (const float*)d_in[7];
    const float* oc_bnb = (const float*)d_in[8];
    const float* oc_bnm = (const float*)d_in[9];
    const float* oc_bnv = (const float*)d_in[10];
    const float* ex_w   = (const float*)d_in[11];
    const float* ey_w   = (const float*)d_in[12];
    const float* ez_w   = (const float*)d_in[13];
    const float* ff_w   = (const float*)d_in[14];
    const float* ff_b   = (const float*)d_in[15];
    const float* g1_w   = (const float*)d_in[16];
    const float* g1_b   = (const float*)d_in[17];
    const float* g2_w   = (const float*)d_in[18];
    const float* g2_b   = (const float*)d_in[19];
    const float* fu_w   = (const float*)d_in[20];
    const float* fu_b   = (const float*)d_in[21];
    const float* fu_bng = (const float*)d_in[22];
    const float* fu_bnb = (const float*)d_in[23];
    const float* fu_bnm = (const float*)d_in[24];
    const float* fu_bnv = (const float*)d_in[25];

    pack_kernel<<<90, 256>>>(sc_w, sc_b, ac_w, ac_b, oc_w, oc_b,
                             oc_bng, oc_bnb, oc_bnm, oc_bnv,
                             fu_w, fu_b, fu_bng, fu_bnb, fu_bnm, fu_bnv);
    fft_energy_kernel<<<BB * CC, 256>>>(x);
    gates_kernel<<<BB, 64>>>(ex_w, ey_w, ez_w, ff_w, ff_b, g1_w, g1_b, g2_w, g2_b);
    rfa_fuse_kernel<<<BB * 32, 128>>>(x, (float*)d_out);
}